// round 6
// baseline (speedup 1.0000x reference)
#include <cuda_runtime.h>

// VectorQuantizer: x (16,2048,256) f32, codebook (1024,256) f32.
// Outputs (concatenated f32 in d_out):
//   [0, N*D)        quantized = x + (cb[idx] - x)   (STE arithmetic mimicked in fp32)
//   [N*D, N*D+N)    indices (as float)
//   [N*D+N]         commitment loss = mean((cb[idx]-x)^2)
//
// Distance mimics reference rounding: d = fl( fl(||x||^2 + ||e||^2) - 2*(x.e) ),
// ties -> lowest index (argmin-first semantics).

#define DDIM   256
#define KMAX   1024
#define NMAX   32768

#define BM 64
#define BN 128
#define BK 16
#define XS_STRIDE 17
#define ES_STRIDE 130

__device__ float  g_sx[NMAX];
__device__ float  g_se[KMAX];
__device__ int    g_idx[NMAX];
__device__ double g_part[NMAX / 8];   // per-block partial loss sums (gather kernel, 8 rows/block)

// ---------------------------------------------------------------------------
// Row sum-of-squares for x (N rows) and codebook (K rows). One warp per row.
// ---------------------------------------------------------------------------
__global__ void stats_kernel(const float* __restrict__ x,
                             const float* __restrict__ cb,
                             int N, int K) {
    int warp = (blockIdx.x * blockDim.x + threadIdx.x) >> 5;
    int lane = threadIdx.x & 31;
    int total = N + K;
    if (warp >= total) return;
    const float* src = (warp < N) ? (x + (size_t)warp * DDIM)
                                  : (cb + (size_t)(warp - N) * DDIM);
    float s = 0.0f;
#pragma unroll
    for (int i = 0; i < DDIM / 32; i++) {
        float v = src[lane + 32 * i];
        s = fmaf(v, v, s);
    }
#pragma unroll
    for (int off = 16; off; off >>= 1)
        s += __shfl_down_sync(0xffffffffu, s, off);
    if (lane == 0) {
        if (warp < N) g_sx[warp] = s;
        else          g_se[warp - N] = s;
    }
}

// ---------------------------------------------------------------------------
// Fused GEMM + argmin. Block tile: 64 rows x 128 codes per chunk, 8 chunks.
// 256 threads (16x16), each thread: 4 rows x 8 cols (4 packed f32x2 pairs).
// Inner product via fma.rn.f32x2 (FFMA2) for 2x fp32 throughput.
// ---------------------------------------------------------------------------
__global__ __launch_bounds__(256, 2)
void argmin_kernel(const float* __restrict__ x,
                   const float* __restrict__ cb,
                   float* __restrict__ out_idx_f,
                   int N, int K) {
    __shared__ __align__(16) float Xs[BM * XS_STRIDE];
    __shared__ __align__(16) float Es[BK * ES_STRIDE];
    __shared__ float red_v[BM * 16];
    __shared__ int   red_i[BM * 16];

    const int tid = threadIdx.x;
    const int tx  = tid & 15;
    const int ty  = tid >> 4;
    const int r0  = blockIdx.x * BM;

    float best[4];
    int   bidx[4];
#pragma unroll
    for (int i = 0; i < 4; i++) { best[i] = 3.4e38f; bidx[i] = 0; }

    float sxr[4];
#pragma unroll
    for (int i = 0; i < 4; i++) sxr[i] = g_sx[r0 + ty * 4 + i];

    for (int n0 = 0; n0 < K; n0 += BN) {
        unsigned long long acc[4][4];
#pragma unroll
        for (int i = 0; i < 4; i++)
#pragma unroll
            for (int j = 0; j < 4; j++) acc[i][j] = 0ull;

        for (int kk = 0; kk < DDIM; kk += BK) {
            __syncthreads();  // protect tiles from previous iteration's readers
            // Load X tile: Xs[row][d], padded stride. Coalesced global reads.
#pragma unroll
            for (int p = 0; p < (BM * BK) / 256; p++) {      // 4 iters
                int idx = tid + p * 256;
                int row = idx >> 4, dd = idx & 15;
                Xs[row * XS_STRIDE + dd] = x[(size_t)(r0 + row) * DDIM + kk + dd];
            }
            // Load E tile: Es[d][col], padded stride. Coalesced global reads.
#pragma unroll
            for (int p = 0; p < (BN * BK) / 256; p++) {      // 8 iters
                int idx = tid + p * 256;
                int dd = idx & 15, col = idx >> 4;
                Es[dd * ES_STRIDE + col] = cb[(size_t)(n0 + col) * DDIM + kk + dd];
            }
            __syncthreads();

#pragma unroll
            for (int dd = 0; dd < BK; dd++) {
                unsigned long long a2[4], b2[4];
#pragma unroll
                for (int i = 0; i < 4; i++) {
                    unsigned int ua = __float_as_uint(Xs[(ty * 4 + i) * XS_STRIDE + dd]);
                    asm("mov.b64 %0, {%1, %1};" : "=l"(a2[i]) : "r"(ua));
                }
#pragma unroll
                for (int j = 0; j < 4; j++)
                    b2[j] = *reinterpret_cast<const unsigned long long*>(
                        &Es[dd * ES_STRIDE + tx * 2 + 32 * j]);
#pragma unroll
                for (int i = 0; i < 4; i++)
#pragma unroll
                    for (int j = 0; j < 4; j++)
                        asm("fma.rn.f32x2 %0, %1, %2, %0;"
                            : "+l"(acc[i][j]) : "l"(a2[i]), "l"(b2[j]));
            }
        }

        // Compare: d = fl( fl(sx + se_k) - 2*dot ), ascending k within thread,
        // strict '<' keeps first (lowest-k) occurrence of the min.
#pragma unroll
        for (int i = 0; i < 4; i++) {
#pragma unroll
            for (int j = 0; j < 4; j++) {
                unsigned int lo, hi;
                asm("mov.b64 {%0, %1}, %2;" : "=r"(lo), "=r"(hi) : "l"(acc[i][j]));
                int k0 = n0 + 32 * j + tx * 2;
                {
                    float t  = sxr[i] + g_se[k0];
                    float dv = fmaf(-2.0f, __uint_as_float(lo), t);  // == fl(t - 2*dot)
                    if (dv < best[i]) { best[i] = dv; bidx[i] = k0; }
                }
                {
                    float t  = sxr[i] + g_se[k0 + 1];
                    float dv = fmaf(-2.0f, __uint_as_float(hi), t);
                    if (dv < best[i]) { best[i] = dv; bidx[i] = k0 + 1; }
                }
            }
        }
    }

    __syncthreads();
#pragma unroll
    for (int i = 0; i < 4; i++) {
        red_v[(ty * 4 + i) * 16 + tx] = best[i];
        red_i[(ty * 4 + i) * 16 + tx] = bidx[i];
    }
    __syncthreads();

    if (tid < BM) {
        float bv = red_v[tid * 16];
        int   bi = red_i[tid * 16];
#pragma unroll
        for (int t = 1; t < 16; t++) {
            float v  = red_v[tid * 16 + t];
            int   id = red_i[tid * 16 + t];
            if (v < bv || (v == bv && id < bi)) { bv = v; bi = id; }
        }
        int row = r0 + tid;
        g_idx[row] = bi;
        out_idx_f[row] = (float)bi;
    }
}

// ---------------------------------------------------------------------------
// Gather quantized rows (STE arithmetic: x + (q - x)), accumulate loss partials.
// One warp per row, 8 rows per block. Deterministic two-stage reduction.
// ---------------------------------------------------------------------------
__global__ void gather_kernel(const float* __restrict__ x,
                              const float* __restrict__ cb,
                              float* __restrict__ out_q,
                              int N) {
    __shared__ double warp_s[8];
    int warp_in_blk = threadIdx.x >> 5;
    int row  = blockIdx.x * 8 + warp_in_blk;
    int lane = threadIdx.x & 31;

    double s = 0.0;
    if (row < N) {
        int idx = g_idx[row];
        const float4* xr = reinterpret_cast<const float4*>(x + (size_t)row * DDIM);
        const float4* qr = reinterpret_cast<const float4*>(cb + (size_t)idx * DDIM);
        float4* orow = reinterpret_cast<float4*>(out_q + (size_t)row * DDIM);
#pragma unroll
        for (int i = 0; i < 2; i++) {
            float4 xv = xr[lane + 32 * i];
            float4 qv = qr[lane + 32 * i];
            float4 o;
            float d0 = qv.x - xv.x; o.x = xv.x + d0; s += (double)d0 * d0;
            float d1 = qv.y - xv.y; o.y = xv.y + d1; s += (double)d1 * d1;
            float d2 = qv.z - xv.z; o.z = xv.z + d2; s += (double)d2 * d2;
            float d3 = qv.w - xv.w; o.w = xv.w + d3; s += (double)d3 * d3;
            orow[lane + 32 * i] = o;
        }
    }
#pragma unroll
    for (int off = 16; off; off >>= 1)
        s += __shfl_down_sync(0xffffffffu, s, off);
    if (lane == 0) warp_s[warp_in_blk] = s;
    __syncthreads();
    if (threadIdx.x == 0) {
        double bs = 0.0;
#pragma unroll
        for (int w = 0; w < 8; w++) bs += warp_s[w];
        g_part[blockIdx.x] = bs;
    }
}

__global__ void finalize_kernel(float* __restrict__ out_loss,
                                int nblocks, long long ND) {
    __shared__ double sm[256];
    double s = 0.0;
    for (int i = threadIdx.x; i < nblocks; i += 256) s += g_part[i];
    sm[threadIdx.x] = s;
    __syncthreads();
    for (int off = 128; off; off >>= 1) {
        if (threadIdx.x < off) sm[threadIdx.x] += sm[threadIdx.x + off];
        __syncthreads();
    }
    if (threadIdx.x == 0) *out_loss = (float)(sm[0] / (double)ND);
}

// ---------------------------------------------------------------------------
extern "C" void kernel_launch(void* const* d_in, const int* in_sizes, int n_in,
                              void* d_out, int out_size) {
    const float* x  = (const float*)d_in[0];
    const float* cb = (const float*)d_in[1];
    int N = in_sizes[0] / DDIM;   // 32768
    int K = in_sizes[1] / DDIM;   // 1024

    float* out   = (float*)d_out;
    float* out_q = out;
    float* out_i = out + (size_t)N * DDIM;
    float* out_l = out + (size_t)N * DDIM + N;

    int stat_blocks = (N + K + 7) / 8;          // 8 warps per block
    stats_kernel<<<stat_blocks, 256>>>(x, cb, N, K);

    argmin_kernel<<<N / BM, 256>>>(x, cb, out_i, N, K);

    int gather_blocks = (N + 7) / 8;
    gather_kernel<<<gather_blocks, 256>>>(x, cb, out_q, N);

    finalize_kernel<<<1, 256>>>(out_l, gather_blocks, (long long)N * DDIM);
}

// round 12
// speedup vs baseline: 1.0183x; 1.0183x over previous
#include <cuda_runtime.h>
#include <cuda_bf16.h>
#include <cstdint>

// VectorQuantizer: x (16,2048,256) f32, codebook (1024,256) f32.
// Outputs (concatenated f32 in d_out):
//   [0, N*D)        quantized = x + (cb[idx] - x)
//   [N*D, N*D+N)    indices (as float)
//   [N*D+N]         commitment loss = mean((cb[idx]-x)^2)
//
// bf16 mma.sync distance pass (manual fragment loads, no ldmatrix/swizzle)
// -> per-row candidate set within a provably-safe margin
// -> exact fp32 refine replicating the validated rounding sequence
//    d = fl( fl(sx+se) - 2*dot_serial ), lowest-index ties.

#define DDIM    256
#define KCODES  1024
#define NROWS   32768

#define BM 128          // rows per block (dist kernel)
#define BN 128          // codes per chunk
#define TS 72           // smem tile row stride in bf16 (144 B: 16B-aligned, conflict-free)
#define CAND_CAP 16
#define MARGIN 6e-3f    // > 2 * worst-case |d_bf16 - d_fp32| (~4.8e-3)

__device__ float  g_sx[NROWS];
__device__ float  g_se[KCODES];
__device__ int    g_idx[NROWS];
__device__ double g_part[NROWS / 8];
__device__ __nv_bfloat16 g_xb[(size_t)NROWS * DDIM];
__device__ __nv_bfloat16 g_eb[(size_t)KCODES * DDIM];
__device__ int    g_cnt[NROWS];
__device__ int    g_cand[NROWS * CAND_CAP];

// ---------------------------------------------------------------------------
// Row sum-of-squares for x and codebook + bf16 conversion. One warp per row.
// ---------------------------------------------------------------------------
__global__ void stats_kernel(const float* __restrict__ x,
                             const float* __restrict__ cb,
                             int N, int K) {
    int warp = (blockIdx.x * blockDim.x + threadIdx.x) >> 5;
    int lane = threadIdx.x & 31;
    if (warp >= N + K) return;
    const float* src;
    __nv_bfloat16* dst;
    if (warp < N) { src = x  + (size_t)warp * DDIM;       dst = g_xb + (size_t)warp * DDIM; }
    else          { src = cb + (size_t)(warp - N) * DDIM; dst = g_eb + (size_t)(warp - N) * DDIM; }
    float s = 0.0f;
#pragma unroll
    for (int i = 0; i < DDIM / 32; i++) {
        float v = src[lane + 32 * i];
        s = fmaf(v, v, s);
        dst[lane + 32 * i] = __float2bfloat16(v);
    }
#pragma unroll
    for (int off = 16; off; off >>= 1)
        s += __shfl_down_sync(0xffffffffu, s, off);
    if (lane == 0) {
        if (warp < N) g_sx[warp] = s;
        else          g_se[warp - N] = s;
    }
}

// ---------------------------------------------------------------------------
// bf16 tensor-core distance pass + per-row min + candidate collection.
// 256 threads (8 warps as 4Mx2N), block tile 128 rows x 128 codes, D in
// chunks of 64. Warp tile 32x64 via mma.sync m16n8k16. Fragments loaded with
// plain 32-bit LDS from unswizzled row-major tiles (stride TS=72 bf16):
//   A reg = Xs[row][k], Xs[row][k+1]  (k-adjacent pair, lo = lower k)
//   B reg = Es[code][k], Es[code][k+1] ("col-major" B == k-contiguous per code)
// Lane map (mma spec): gr = lane>>2, j = lane&3.
//   A: a0=(gr,   2j), a1=(gr+8, 2j), a2=(gr,   2j+8), a3=(gr+8, 2j+8)  [+k16 base]
//   B: b0=(n=gr, k=2j), b1=(n=gr, k=2j+8)
//   C: c0=(gr, 2j), c1=(gr, 2j+1), c2=(gr+8, 2j), c3=(gr+8, 2j+1)
// ---------------------------------------------------------------------------
__global__ __launch_bounds__(256, 2)
void dist_kernel() {
    __shared__ __align__(16) __nv_bfloat16 Xs[BM * TS];
    __shared__ __align__(16) __nv_bfloat16 Es[BN * TS];
    __shared__ float    sxs[BM];
    __shared__ float    ses[BN];
    __shared__ unsigned rmin[BM];
    __shared__ int      cnt[BM];
    __shared__ int      lst[BM * CAND_CAP];

    const int tid  = threadIdx.x;
    const int lane = tid & 31;
    const int wid  = tid >> 5;
    const int wm   = wid >> 1;        // 0..3 along M (32 rows each)
    const int wn   = wid & 1;         // 0..1 along N (64 codes each)
    const int r0   = blockIdx.x * BM;

    const int gr = lane >> 2;         // 0..7
    const int gj = lane & 3;          // 0..3

    if (tid < BM) {
        sxs[tid]  = g_sx[r0 + tid];
        rmin[tid] = 0x7f7fffffu;      // FLT_MAX bits (all d > 0 here)
        cnt[tid]  = 0;
    }

    for (int n0 = 0; n0 < KCODES; n0 += BN) {
        __syncthreads();   // init / previous epilogue done before ses overwrite
        if (tid < BN) ses[tid] = g_se[n0 + tid];

        float acc[2][8][4];
#pragma unroll
        for (int mi = 0; mi < 2; mi++)
#pragma unroll
            for (int ni = 0; ni < 8; ni++)
#pragma unroll
                for (int q = 0; q < 4; q++) acc[mi][ni][q] = 0.0f;

        for (int kt = 0; kt < 4; kt++) {
            const int kk = kt * 64;
            __syncthreads();
            // Load X and E tiles (128 x 64 bf16 each) as uint4 (8 bf16) chunks.
#pragma unroll
            for (int p = 0; p < 4; p++) {
                int idx = tid + p * 256;           // 1024 uint4 per tile
                int r = idx >> 3, q = idx & 7;
                *(uint4*)(Xs + r * TS + q * 8) =
                    *(const uint4*)(g_xb + (size_t)(r0 + r) * DDIM + kk + q * 8);
                *(uint4*)(Es + r * TS + q * 8) =
                    *(const uint4*)(g_eb + (size_t)(n0 + r) * DDIM + kk + q * 8);
            }
            __syncthreads();

#pragma unroll
            for (int ks = 0; ks < 4; ks++) {
                const int kb = ks * 16;
                unsigned a[2][4];
#pragma unroll
                for (int mi = 0; mi < 2; mi++) {
                    const __nv_bfloat16* ar =
                        Xs + (wm * 32 + mi * 16 + gr) * TS + kb + 2 * gj;
                    a[mi][0] = *(const unsigned*)(ar);
                    a[mi][1] = *(const unsigned*)(ar + 8 * TS);
                    a[mi][2] = *(const unsigned*)(ar + 8);
                    a[mi][3] = *(const unsigned*)(ar + 8 * TS + 8);
                }
#pragma unroll
                for (int ni = 0; ni < 8; ni++) {
                    const __nv_bfloat16* br =
                        Es + (wn * 64 + ni * 8 + gr) * TS + kb + 2 * gj;
                    unsigned b0 = *(const unsigned*)(br);
                    unsigned b1 = *(const unsigned*)(br + 8);
#pragma unroll
                    for (int mi = 0; mi < 2; mi++) {
                        asm volatile(
                            "mma.sync.aligned.m16n8k16.row.col.f32.bf16.bf16.f32 "
                            "{%0,%1,%2,%3},{%4,%5,%6,%7},{%8,%9},{%0,%1,%2,%3};"
                            : "+f"(acc[mi][ni][0]), "+f"(acc[mi][ni][1]),
                              "+f"(acc[mi][ni][2]), "+f"(acc[mi][ni][3])
                            : "r"(a[mi][0]), "r"(a[mi][1]), "r"(a[mi][2]), "r"(a[mi][3]),
                              "r"(b0), "r"(b1));
                    }
                }
            }
        }

        // Epilogue pass 1: acc -> approx distance, per-row running min.
        const int gc = gj * 2;
#pragma unroll
        for (int mi = 0; mi < 2; mi++) {
#pragma unroll
            for (int h = 0; h < 2; h++) {          // h=0 -> c0,c1 (row gr); h=1 -> c2,c3 (row gr+8)
                int row = wm * 32 + mi * 16 + gr + 8 * h;
                float t0 = sxs[row];
                float dm = 3.4e38f;
#pragma unroll
                for (int ni = 0; ni < 8; ni++) {
                    int col = wn * 64 + ni * 8 + gc;
                    float d0 = fmaf(-2.0f, acc[mi][ni][2*h],   t0 + ses[col]);
                    float d1 = fmaf(-2.0f, acc[mi][ni][2*h+1], t0 + ses[col+1]);
                    acc[mi][ni][2*h]   = d0;
                    acc[mi][ni][2*h+1] = d1;
                    dm = fminf(dm, fminf(d0, d1));
                }
                atomicMin(&rmin[row], __float_as_uint(dm));
            }
        }
        __syncthreads();
        // Epilogue pass 2: collect candidates within MARGIN of running min.
#pragma unroll
        for (int mi = 0; mi < 2; mi++) {
#pragma unroll
            for (int h = 0; h < 2; h++) {
                int row = wm * 32 + mi * 16 + gr + 8 * h;
                float thr = __uint_as_float(rmin[row]) + MARGIN;
#pragma unroll
                for (int ni = 0; ni < 8; ni++) {
#pragma unroll
                    for (int q = 0; q < 2; q++) {
                        float d = acc[mi][ni][2*h + q];
                        if (d <= thr) {
                            int pos = atomicAdd(&cnt[row], 1);
                            if (pos < CAND_CAP)
                                lst[row * CAND_CAP + pos] = n0 + wn * 64 + ni * 8 + gc + q;
                        }
                    }
                }
            }
        }
    }

    __syncthreads();
    if (tid < BM) {
        int row = r0 + tid;
        int c = cnt[tid];
        g_cnt[row] = c;
        int m = c < CAND_CAP ? c : CAND_CAP;
        for (int j = 0; j < m; j++)
            g_cand[row * CAND_CAP + j] = lst[tid * CAND_CAP + j];
    }
}

// ---------------------------------------------------------------------------
// Exact refine: one warp per row, one candidate per lane. Bit-identical to the
// validated fp32 formula: serial fmaf dot over d=0..255, d = fmaf(-2,dot,sx+se),
// lowest-index ties. Fallback on candidate overflow: full exact scan.
// ---------------------------------------------------------------------------
__device__ __forceinline__ float exact_dist(const float4* __restrict__ xr,
                                            const float* __restrict__ cb,
                                            float sx, int k) {
    const float4* er = (const float4*)(cb + (size_t)k * DDIM);
    float dot = 0.0f;
#pragma unroll 8
    for (int i = 0; i < DDIM / 4; i++) {
        float4 a = xr[i], b = er[i];
        dot = fmaf(a.x, b.x, dot);
        dot = fmaf(a.y, b.y, dot);
        dot = fmaf(a.z, b.z, dot);
        dot = fmaf(a.w, b.w, dot);
    }
    return fmaf(-2.0f, dot, sx + g_se[k]);
}

__global__ void refine_kernel(const float* __restrict__ x,
                              const float* __restrict__ cb,
                              float* __restrict__ out_idx_f) {
    int row  = (blockIdx.x * blockDim.x + threadIdx.x) >> 5;
    int lane = threadIdx.x & 31;
    if (row >= NROWS) return;

    const float4* xr = (const float4*)(x + (size_t)row * DDIM);
    float sx = g_sx[row];
    int c = g_cnt[row];

    float bd = 3.4e38f;
    int   bk = 0x7fffffff;
    if (c <= CAND_CAP) {
        if (lane < c) {
            int k = g_cand[row * CAND_CAP + lane];
            bd = exact_dist(xr, cb, sx, k);
            bk = k;
        }
    } else {
        for (int k = lane; k < KCODES; k += 32) {
            float d = exact_dist(xr, cb, sx, k);
            if (d < bd || (d == bd && k < bk)) { bd = d; bk = k; }
        }
    }
#pragma unroll
    for (int off = 16; off; off >>= 1) {
        float od = __shfl_down_sync(0xffffffffu, bd, off);
        int   ok = __shfl_down_sync(0xffffffffu, bk, off);
        if (od < bd || (od == bd && ok < bk)) { bd = od; bk = ok; }
    }
    if (lane == 0) {
        g_idx[row] = bk;
        out_idx_f[row] = (float)bk;
    }
}

// ---------------------------------------------------------------------------
// Gather quantized rows (STE arithmetic) + deterministic loss partials.
// ---------------------------------------------------------------------------
__global__ void gather_kernel(const float* __restrict__ x,
                              const float* __restrict__ cb,
                              float* __restrict__ out_q,
                              int N) {
    __shared__ double warp_s[8];
    int warp_in_blk = threadIdx.x >> 5;
    int row  = blockIdx.x * 8 + warp_in_blk;
    int lane = threadIdx.x & 31;

    double s = 0.0;
    if (row < N) {
        int idx = g_idx[row];
        const float4* xr = reinterpret_cast<const float4*>(x + (size_t)row * DDIM);
        const float4* qr = reinterpret_cast<const float4*>(cb + (size_t)idx * DDIM);
        float4* orow = reinterpret_cast<float4*>(out_q + (size_t)row * DDIM);
#pragma unroll
        for (int i = 0; i < 2; i++) {
            float4 xv = xr[lane + 32 * i];
            float4 qv = qr[lane + 32 * i];
            float4 o;
            float d0 = qv.x - xv.x; o.x = xv.x + d0; s += (double)d0 * d0;
            float d1 = qv.y - xv.y; o.y = xv.y + d1; s += (double)d1 * d1;
            float d2 = qv.z - xv.z; o.z = xv.z + d2; s += (double)d2 * d2;
            float d3 = qv.w - xv.w; o.w = xv.w + d3; s += (double)d3 * d3;
            orow[lane + 32 * i] = o;
        }
    }
#pragma unroll
    for (int off = 16; off; off >>= 1)
        s += __shfl_down_sync(0xffffffffu, s, off);
    if (lane == 0) warp_s[warp_in_blk] = s;
    __syncthreads();
    if (threadIdx.x == 0) {
        double bs = 0.0;
#pragma unroll
        for (int w = 0; w < 8; w++) bs += warp_s[w];
        g_part[blockIdx.x] = bs;
    }
}

__global__ void finalize_kernel(float* __restrict__ out_loss,
                                int nblocks, long long ND) {
    __shared__ double sm[256];
    double s = 0.0;
    for (int i = threadIdx.x; i < nblocks; i += 256) s += g_part[i];
    sm[threadIdx.x] = s;
    __syncthreads();
    for (int off = 128; off; off >>= 1) {
        if (threadIdx.x < off) sm[threadIdx.x] += sm[threadIdx.x + off];
        __syncthreads();
    }
    if (threadIdx.x == 0) *out_loss = (float)(sm[0] / (double)ND);
}

// ---------------------------------------------------------------------------
extern "C" void kernel_launch(void* const* d_in, const int* in_sizes, int n_in,
                              void* d_out, int out_size) {
    const float* x  = (const float*)d_in[0];
    const float* cb = (const float*)d_in[1];
    int N = in_sizes[0] / DDIM;   // 32768
    int K = in_sizes[1] / DDIM;   // 1024

    float* out   = (float*)d_out;
    float* out_q = out;
    float* out_i = out + (size_t)N * DDIM;
    float* out_l = out + (size_t)N * DDIM + N;

    stats_kernel<<<(N + K + 7) / 8, 256>>>(x, cb, N, K);
    dist_kernel<<<N / BM, 256>>>();
    refine_kernel<<<(N * 32 + 255) / 256, 256>>>(x, cb, out_i);

    int gather_blocks = (N + 7) / 8;
    gather_kernel<<<gather_blocks, 256>>>(x, cb, out_q, N);
    finalize_kernel<<<1, 256>>>(out_l, gather_blocks, (long long)N * DDIM);
}

// round 15
// speedup vs baseline: 1.0281x; 1.0096x over previous
#include <cuda_runtime.h>
#include <cuda_bf16.h>
#include <cstdint>

// VectorQuantizer: x (16,2048,256) f32, codebook (1024,256) f32.
// Outputs (concatenated f32 in d_out):
//   [0, N*D)        quantized = x + (cb[idx] - x)
//   [N*D, N*D+N)    indices (as float)
//   [N*D+N]         commitment loss = mean((cb[idx]-x)^2)
//
// bf16 mma.sync distance pass (512-thread CTAs for HMMA latency hiding)
// -> per-row candidate set within a provably-safe margin
// -> exact fp32 refine (validated rounding sequence, lowest-index ties)
//    fused with the quantized gather + loss partials.
//
// NOTE: toolchain targets compute_103 (no 'a') -> tcgen05 unavailable;
// baseline-PTX mma.sync only.

#define DDIM    256
#define KCODES  1024
#define NROWS   32768

#define BM 128          // rows per block (dist kernel)
#define BN 128          // codes per chunk
#define TS 72           // smem tile row stride in bf16 (144 B: 16B-aligned, conflict-free)
#define CAND_CAP 16
#define MARGIN 6e-3f    // > 2 * worst-case |d_bf16 - d_fp32| (~4.8e-3)

__device__ float  g_sx[NROWS];
__device__ float  g_se[KCODES];
__device__ double g_part[NROWS];
__device__ __nv_bfloat16 g_xb[(size_t)NROWS * DDIM];
__device__ __nv_bfloat16 g_eb[(size_t)KCODES * DDIM];
__device__ int    g_cnt[NROWS];
__device__ int    g_cand[NROWS * CAND_CAP];

// ---------------------------------------------------------------------------
// Row sum-of-squares for x and codebook + bf16 conversion. One warp per row.
// ---------------------------------------------------------------------------
__global__ void stats_kernel(const float* __restrict__ x,
                             const float* __restrict__ cb,
                             int N, int K) {
    int warp = (blockIdx.x * blockDim.x + threadIdx.x) >> 5;
    int lane = threadIdx.x & 31;
    if (warp >= N + K) return;
    const float* src;
    __nv_bfloat16* dst;
    if (warp < N) { src = x  + (size_t)warp * DDIM;       dst = g_xb + (size_t)warp * DDIM; }
    else          { src = cb + (size_t)(warp - N) * DDIM; dst = g_eb + (size_t)(warp - N) * DDIM; }
    float s = 0.0f;
#pragma unroll
    for (int i = 0; i < DDIM / 32; i++) {
        float v = src[lane + 32 * i];
        s = fmaf(v, v, s);
        dst[lane + 32 * i] = __float2bfloat16(v);
    }
#pragma unroll
    for (int off = 16; off; off >>= 1)
        s += __shfl_down_sync(0xffffffffu, s, off);
    if (lane == 0) {
        if (warp < N) g_sx[warp] = s;
        else          g_se[warp - N] = s;
    }
}

// ---------------------------------------------------------------------------
// bf16 tensor-core distance pass + per-row min + candidate collection.
// 512 threads (16 warps as 8M x 2N), block tile 128 rows x 128 codes, D in
// chunks of 64. Warp tile 16x64: 8 n-frags of mma.sync m16n8k16, acc=32 regs
// (reused in-place by the epilogue -> no spills at 64-reg budget).
// Fragment geometry identical to the validated R12 kernel:
//   A reg = Xs[row][k..k+1], B reg = Es[code][k..k+1] (k-adjacent pairs),
//   gr = lane>>2, gj = lane&3.
// ---------------------------------------------------------------------------
__global__ __launch_bounds__(512, 2)
void dist_kernel() {
    __shared__ __align__(16) __nv_bfloat16 Xs[BM * TS];
    __shared__ __align__(16) __nv_bfloat16 Es[BN * TS];
    __shared__ float    sxs[BM];
    __shared__ float    ses[BN];
    __shared__ unsigned rmin[BM];
    __shared__ int      cnt[BM];
    __shared__ int      lst[BM * CAND_CAP];

    const int tid  = threadIdx.x;
    const int lane = tid & 31;
    const int wid  = tid >> 5;
    const int wm   = wid >> 1;        // 0..7 along M (16 rows each)
    const int wn   = wid & 1;         // 0..1 along N (64 codes each)
    const int r0   = blockIdx.x * BM;

    const int gr = lane >> 2;         // 0..7
    const int gj = lane & 3;          // 0..3

    if (tid < BM) {
        sxs[tid]  = g_sx[r0 + tid];
        rmin[tid] = 0x7f7fffffu;      // FLT_MAX bits (all d > 0 here)
        cnt[tid]  = 0;
    }

    for (int n0 = 0; n0 < KCODES; n0 += BN) {
        __syncthreads();   // init / previous epilogue done before ses overwrite
        if (tid < BN) ses[tid] = g_se[n0 + tid];

        float acc[8][4];
#pragma unroll
        for (int ni = 0; ni < 8; ni++)
#pragma unroll
            for (int q = 0; q < 4; q++) acc[ni][q] = 0.0f;

        for (int kt = 0; kt < 4; kt++) {
            const int kk = kt * 64;
            __syncthreads();
            // Load X and E tiles (128 x 64 bf16 each) as uint4 (8 bf16) chunks.
#pragma unroll
            for (int p = 0; p < 2; p++) {
                int idx = tid + p * 512;           // 1024 uint4 per tile
                int r = idx >> 3, q = idx & 7;
                *(uint4*)(Xs + r * TS + q * 8) =
                    *(const uint4*)(g_xb + (size_t)(r0 + r) * DDIM + kk + q * 8);
                *(uint4*)(Es + r * TS + q * 8) =
                    *(const uint4*)(g_eb + (size_t)(n0 + r) * DDIM + kk + q * 8);
            }
            __syncthreads();

#pragma unroll
            for (int ks = 0; ks < 4; ks++) {
                const int kb = ks * 16;
                unsigned a[4];
                {
                    const __nv_bfloat16* ar = Xs + (wm * 16 + gr) * TS + kb + 2 * gj;
                    a[0] = *(const unsigned*)(ar);
                    a[1] = *(const unsigned*)(ar + 8 * TS);
                    a[2] = *(const unsigned*)(ar + 8);
                    a[3] = *(const unsigned*)(ar + 8 * TS + 8);
                }
#pragma unroll
                for (int ni = 0; ni < 8; ni++) {
                    const __nv_bfloat16* br =
                        Es + (wn * 64 + ni * 8 + gr) * TS + kb + 2 * gj;
                    unsigned b0 = *(const unsigned*)(br);
                    unsigned b1 = *(const unsigned*)(br + 8);
                    asm volatile(
                        "mma.sync.aligned.m16n8k16.row.col.f32.bf16.bf16.f32 "
                        "{%0,%1,%2,%3},{%4,%5,%6,%7},{%8,%9},{%0,%1,%2,%3};"
                        : "+f"(acc[ni][0]), "+f"(acc[ni][1]),
                          "+f"(acc[ni][2]), "+f"(acc[ni][3])
                        : "r"(a[0]), "r"(a[1]), "r"(a[2]), "r"(a[3]),
                          "r"(b0), "r"(b1));
                }
            }
        }

        // Epilogue pass 1: acc -> approx distance (in place), per-row min.
        const int gc = gj * 2;
#pragma unroll
        for (int h = 0; h < 2; h++) {   // h=0 -> c0,c1 (row gr); h=1 -> c2,c3 (row gr+8)
            int row = wm * 16 + gr + 8 * h;
            float t0 = sxs[row];
            float dm = 3.4e38f;
#pragma unroll
            for (int ni = 0; ni < 8; ni++) {
                int col = wn * 64 + ni * 8 + gc;
                float d0 = fmaf(-2.0f, acc[ni][2*h],   t0 + ses[col]);
                float d1 = fmaf(-2.0f, acc[ni][2*h+1], t0 + ses[col+1]);
                acc[ni][2*h]   = d0;
                acc[ni][2*h+1] = d1;
                dm = fminf(dm, fminf(d0, d1));
            }
            atomicMin(&rmin[row], __float_as_uint(dm));
        }
        __syncthreads();
        // Epilogue pass 2: collect candidates within MARGIN of running min.
#pragma unroll
        for (int h = 0; h < 2; h++) {
            int row = wm * 16 + gr + 8 * h;
            float thr = __uint_as_float(rmin[row]) + MARGIN;
#pragma unroll
            for (int ni = 0; ni < 8; ni++) {
#pragma unroll
                for (int q = 0; q < 2; q++) {
                    float d = acc[ni][2*h + q];
                    if (d <= thr) {
                        int pos = atomicAdd(&cnt[row], 1);
                        if (pos < CAND_CAP)
                            lst[row * CAND_CAP + pos] = n0 + wn * 64 + ni * 8 + gc + q;
                    }
                }
            }
        }
    }

    __syncthreads();
    if (tid < BM) {
        int row = r0 + tid;
        int c = cnt[tid];
        g_cnt[row] = c;
        int m = c < CAND_CAP ? c : CAND_CAP;
        for (int j = 0; j < m; j++)
            g_cand[row * CAND_CAP + j] = lst[tid * CAND_CAP + j];
    }
}

// ---------------------------------------------------------------------------
// Exact refine + fused gather. One warp per row. Refine is bit-identical to
// the validated fp32 formula: serial fmaf dot over d=0..255,
// d = fmaf(-2,dot,sx+se), lowest-index ties. Overflow -> full exact scan.
// Then the warp gathers quantized = x + (q - x), writes out_q, and emits a
// per-row double loss partial (deterministic).
// ---------------------------------------------------------------------------
__device__ __forceinline__ float exact_dist(const float4* __restrict__ xr,
                                            const float* __restrict__ cb,
                                            float sx, int k) {
    const float4* er = (const float4*)(cb + (size_t)k * DDIM);
    float dot = 0.0f;
#pragma unroll 8
    for (int i = 0; i < DDIM / 4; i++) {
        float4 a = xr[i], b = er[i];
        dot = fmaf(a.x, b.x, dot);
        dot = fmaf(a.y, b.y, dot);
        dot = fmaf(a.z, b.z, dot);
        dot = fmaf(a.w, b.w, dot);
    }
    return fmaf(-2.0f, dot, sx + g_se[k]);
}

__global__ void refine_gather_kernel(const float* __restrict__ x,
                                     const float* __restrict__ cb,
                                     float* __restrict__ out_idx_f,
                                     float* __restrict__ out_q) {
    int row  = (blockIdx.x * blockDim.x + threadIdx.x) >> 5;
    int lane = threadIdx.x & 31;
    if (row >= NROWS) return;

    const float4* xr = (const float4*)(x + (size_t)row * DDIM);
    float sx = g_sx[row];
    int c = g_cnt[row];

    float bd = 3.4e38f;
    int   bk = 0x7fffffff;
    if (c <= CAND_CAP) {
        if (lane < c) {
            int k = g_cand[row * CAND_CAP + lane];
            bd = exact_dist(xr, cb, sx, k);
            bk = k;
        }
    } else {
        for (int k = lane; k < KCODES; k += 32) {
            float d = exact_dist(xr, cb, sx, k);
            if (d < bd || (d == bd && k < bk)) { bd = d; bk = k; }
        }
    }
#pragma unroll
    for (int off = 16; off; off >>= 1) {
        float od = __shfl_down_sync(0xffffffffu, bd, off);
        int   ok = __shfl_down_sync(0xffffffffu, bk, off);
        if (od < bd || (od == bd && ok < bk)) { bd = od; bk = ok; }
    }
    bk = __shfl_sync(0xffffffffu, bk, 0);
    if (lane == 0) out_idx_f[row] = (float)bk;

    // fused gather + loss partial
    const float4* qr = (const float4*)(cb + (size_t)bk * DDIM);
    float4* orow = (float4*)(out_q + (size_t)row * DDIM);
    double s = 0.0;
#pragma unroll
    for (int i = 0; i < 2; i++) {
        float4 xv = xr[lane + 32 * i];
        float4 qv = qr[lane + 32 * i];
        float4 o;
        float e0 = qv.x - xv.x; o.x = xv.x + e0; s += (double)e0 * e0;
        float e1 = qv.y - xv.y; o.y = xv.y + e1; s += (double)e1 * e1;
        float e2 = qv.z - xv.z; o.z = xv.z + e2; s += (double)e2 * e2;
        float e3 = qv.w - xv.w; o.w = xv.w + e3; s += (double)e3 * e3;
        orow[lane + 32 * i] = o;
    }
#pragma unroll
    for (int off = 16; off; off >>= 1)
        s += __shfl_down_sync(0xffffffffu, s, off);
    if (lane == 0) g_part[row] = s;
}

__global__ void finalize_kernel(float* __restrict__ out_loss, int N, long long ND) {
    __shared__ double sm[256];
    double s = 0.0;
    for (int i = threadIdx.x; i < N; i += 256) s += g_part[i];
    sm[threadIdx.x] = s;
    __syncthreads();
    for (int off = 128; off; off >>= 1) {
        if (threadIdx.x < off) sm[threadIdx.x] += sm[threadIdx.x + off];
        __syncthreads();
    }
    if (threadIdx.x == 0) *out_loss = (float)(sm[0] / (double)ND);
}

// ---------------------------------------------------------------------------
extern "C" void kernel_launch(void* const* d_in, const int* in_sizes, int n_in,
                              void* d_out, int out_size) {
    const float* x  = (const float*)d_in[0];
    const float* cb = (const float*)d_in[1];
    int N = in_sizes[0] / DDIM;   // 32768
    int K = in_sizes[1] / DDIM;   // 1024

    float* out   = (float*)d_out;
    float* out_q = out;
    float* out_i = out + (size_t)N * DDIM;
    float* out_l = out + (size_t)N * DDIM + N;

    stats_kernel<<<(N + K + 7) / 8, 256>>>(x, cb, N, K);
    dist_kernel<<<N / BM, 512>>>();
    refine_gather_kernel<<<(N * 32 + 255) / 256, 256>>>(x, cb, out_i, out_q);
    finalize_kernel<<<1, 256>>>(out_l, N, (long long)N * DDIM);
}